// round 3
// baseline (speedup 1.0000x reference)
#include <cuda_runtime.h>

typedef unsigned long long u64;

// ---- packed fp32x2 helpers (sm_103a FFMA2 path) ----
__device__ __forceinline__ u64 pack2(float x, float y) {
    u64 r; asm("mov.b64 %0, {%1, %2};" : "=l"(r) : "f"(x), "f"(y)); return r;
}
__device__ __forceinline__ void unpack2(u64 v, float& x, float& y) {
    asm("mov.b64 {%0, %1}, %2;" : "=f"(x), "=f"(y) : "l"(v));
}
__device__ __forceinline__ u64 ffma2(u64 a, u64 b, u64 c) {
    u64 d; asm("fma.rn.f32x2 %0, %1, %2, %3;" : "=l"(d) : "l"(a), "l"(b), "l"(c)); return d;
}
__device__ __forceinline__ u64 fadd2(u64 a, u64 b) {
    u64 d; asm("add.rn.f32x2 %0, %1, %2;" : "=l"(d) : "l"(a), "l"(b)); return d;
}

__device__ __forceinline__ float fast_sig(float x) {
    return __fdividef(1.0f, 1.0f + __expf(-x));
}
__device__ __forceinline__ float fast_tanh(float x) {
    return __fdividef(2.0f, 1.0f + __expf(-2.0f * x)) - 1.0f;
}

constexpr int S_LEN = 200;
constexpr int BINS  = 256;   // T steps
constexpr int H     = 64;

// One CTA per batch row. 256 threads:
//   thread = (u, kq), u = tid & 63 (hidden unit), kq = tid >> 6 (k-quarter).
// Each thread accumulates packed gate pairs (i,f) and (g,o) of unit u over
// k in [kq*16, kq*16+16). kq>0 partials reduced via SMEM; kq==0 warps apply
// activations, update (c, h) in registers, publish duplicated h to SMEM.
__global__ __launch_bounds__(256, 2)
void trend_lstm_kernel(const float* __restrict__ time_,
                       const int*   __restrict__ length_,
                       const float* __restrict__ predict_time_,
                       const float* __restrict__ W_ih,
                       const float* __restrict__ W_hh,
                       const float* __restrict__ b_ih,
                       const float* __restrict__ b_hh,
                       float* __restrict__ out)
{
    __shared__ float      hist[BINS];
    __shared__ u64        h2s[H];           // (h[k], h[k]) duplicated
    __shared__ ulonglong2 partial[3 * H];   // kq=1..3 partial (accIF, accGO)

    const int tid = threadIdx.x;
    const int row = blockIdx.x;
    const int u   = tid & 63;
    const int kq  = tid >> 6;

    // ---- init SMEM state ----
    hist[tid] = 0.0f;
    if (tid < H) h2s[tid] = 0ull;   // h0 = 0
    __syncthreads();

    // ---- fused histogram (exact replica of reference float math) ----
    const float pt  = predict_time_[row];
    const int   len = length_[row];
    for (int s = tid; s < len; s += 256) {
        float tt  = time_[row * S_LEN + s];
        int   pos = (int)((pt - tt) * 0.25f);   // == /4.0f exactly; trunc-to-zero
        if (pos >= 0 && pos < BINS) atomicAdd(&hist[BINS - 1 - pos], 1.0f);
    }

    // ---- load recurrent weights into registers (packed pairs) ----
    u64 wIF[16], wGO[16];
    const int kb = kq * 16;
#pragma unroll
    for (int kk = 0; kk < 16; kk++) {
        int k = kb + kk;
        wIF[kk] = pack2(W_hh[u * H + k],          W_hh[(64  + u) * H + k]);
        wGO[kk] = pack2(W_hh[(128 + u) * H + k],  W_hh[(192 + u) * H + k]);
    }
    u64 wihIF = 0, wihGO = 0, bIF = 0, bGO = 0;
    if (kq == 0) {
        wihIF = pack2(W_ih[u],        W_ih[64 + u]);
        wihGO = pack2(W_ih[128 + u],  W_ih[192 + u]);
        bIF   = pack2(b_ih[u]       + b_hh[u],       b_ih[64 + u]  + b_hh[64 + u]);
        bGO   = pack2(b_ih[128 + u] + b_hh[128 + u], b_ih[192 + u] + b_hh[192 + u]);
    }

    float c = 0.0f, hout = 0.0f;
    __syncthreads();   // hist + h2s + weights ready

    const ulonglong2* __restrict__ h2v = reinterpret_cast<const ulonglong2*>(h2s);
    const int hv_base = kb >> 1;   // 8 x LDS.128 per thread per step

    for (int t = 0; t < BINS; t++) {
        u64 accIF, accGO;
        if (kq == 0) {
            float x  = hist[t];
            u64   x2 = pack2(x, x);
            accIF = ffma2(x2, wihIF, bIF);
            accGO = ffma2(x2, wihGO, bGO);
        } else {
            accIF = 0ull;   // packed (0.f, 0.f)
            accGO = 0ull;
        }

#pragma unroll
        for (int i = 0; i < 8; i++) {
            ulonglong2 hh = h2v[hv_base + i];   // broadcast LDS.128
            accIF = ffma2(hh.x, wIF[2 * i],     accIF);
            accGO = ffma2(hh.x, wGO[2 * i],     accGO);
            accIF = ffma2(hh.y, wIF[2 * i + 1], accIF);
            accGO = ffma2(hh.y, wGO[2 * i + 1], accGO);
        }

        if (kq > 0) partial[(kq - 1) * H + u] = make_ulonglong2(accIF, accGO);
        __syncthreads();

        if (kq == 0) {
#pragma unroll
            for (int m = 0; m < 3; m++) {
                ulonglong2 p = partial[m * H + u];
                accIF = fadd2(accIF, p.x);
                accGO = fadd2(accGO, p.y);
            }
            float gi, gf, gg, go;
            unpack2(accIF, gi, gf);
            unpack2(accGO, gg, go);
            float si = fast_sig(gi);
            float sf = fast_sig(gf);
            float tg = fast_tanh(gg);
            float so = fast_sig(go);
            c    = sf * c + si * tg;
            hout = so * fast_tanh(c);
            h2s[u] = pack2(hout, hout);
        }
        __syncthreads();
    }

    if (kq == 0) out[row * H + u] = hout;
}

extern "C" void kernel_launch(void* const* d_in, const int* in_sizes, int n_in,
                              void* d_out, int out_size)
{
    const float* time_  = (const float*)d_in[0];   // [4096, 200]
    const int*   length = (const int*)  d_in[1];   // [4096]
    const float* ptime  = (const float*)d_in[2];   // [4096]
    const float* W_ih   = (const float*)d_in[3];   // [256, 1]
    const float* W_hh   = (const float*)d_in[4];   // [256, 64]
    const float* b_ih   = (const float*)d_in[5];   // [256]
    const float* b_hh   = (const float*)d_in[6];   // [256]
    float* out = (float*)d_out;                    // [4096, 64]

    const int B = in_sizes[1];                     // 4096 rows
    trend_lstm_kernel<<<B, 256>>>(time_, length, ptime,
                                  W_ih, W_hh, b_ih, b_hh, out);
}

// round 4
// speedup vs baseline: 1.2895x; 1.2895x over previous
#include <cuda_runtime.h>

typedef unsigned long long u64;

// ---- packed fp32x2 helpers (sm_103a FFMA2 path) ----
__device__ __forceinline__ u64 pack2(float x, float y) {
    u64 r; asm("mov.b64 %0, {%1, %2};" : "=l"(r) : "f"(x), "f"(y)); return r;
}
__device__ __forceinline__ void unpack2(u64 v, float& x, float& y) {
    asm("mov.b64 {%0, %1}, %2;" : "=f"(x), "=f"(y) : "l"(v));
}
__device__ __forceinline__ u64 ffma2(u64 a, u64 b, u64 c) {
    u64 d; asm("fma.rn.f32x2 %0, %1, %2, %3;" : "=l"(d) : "l"(a), "l"(b), "l"(c)); return d;
}
__device__ __forceinline__ u64 fadd2(u64 a, u64 b) {
    u64 d; asm("add.rn.f32x2 %0, %1, %2;" : "=l"(d) : "l"(a), "l"(b)); return d;
}

// HW tanh (single MUFU op on sm_75+; fast path on sm_103a)
__device__ __forceinline__ float htanh(float x) {
    float y; asm("tanh.approx.f32 %0, %1;" : "=f"(y) : "f"(x)); return y;
}
__device__ __forceinline__ float hsig(float x) {
    // sigmoid(x) = 0.5*tanh(0.5x) + 0.5   (1 MUFU + 1 FMA)
    return fmaf(0.5f, htanh(0.5f * x), 0.5f);
}

constexpr int S_LEN = 200;
constexpr int BINS  = 256;   // T steps
constexpr int H     = 64;
constexpr int ROWS  = 4;     // batch rows per CTA

// 256 threads: thread = (u, kq); u = tid & 63 (hidden unit), kq = tid >> 6
// (k-quarter AND "owned row" for the reduce/activation phase).
// Per step, each thread accumulates packed gate pairs (i,f),(g,o) of unit u
// over k in [kq*16, kq*16+16) for ALL 4 rows (same weight registers).
// Cross-slice reduction via SMEM; thread (u, kq) then reduces + activates
// row r = kq, so all 8 warps do MUFU work in parallel.
__global__ __launch_bounds__(256, 2)
void trend_lstm_kernel(const float* __restrict__ time_,
                       const int*   __restrict__ length_,
                       const float* __restrict__ predict_time_,
                       const float* __restrict__ W_ih,
                       const float* __restrict__ W_hh,
                       const float* __restrict__ b_ih,
                       const float* __restrict__ b_hh,
                       float* __restrict__ out)
{
    __shared__ float      hist[ROWS][BINS];
    __shared__ u64        h2s[ROWS][H];            // (h[k], h[k]) duplicated
    __shared__ ulonglong2 partial[ROWS][3][H];     // foreign-slice partials

    const int tid  = threadIdx.x;
    const int u    = tid & 63;
    const int kq   = tid >> 6;
    const int row0 = blockIdx.x * ROWS;

    // ---- init SMEM ----
    {
        float* hf = &hist[0][0];
#pragma unroll
        for (int i = 0; i < ROWS; i++) hf[i * 256 + tid] = 0.0f;
        ((u64*)h2s)[tid] = 0ull;     // ROWS*H == 256 entries; h0 = 0
    }
    __syncthreads();

    // ---- fused histogram: 64 threads (lane u) per row kq ----
    {
        const int   r   = kq;
        const float pt  = predict_time_[row0 + r];
        const int   len = length_[row0 + r];
        const float* tr = time_ + (size_t)(row0 + r) * S_LEN;
        for (int s = u; s < len; s += 64) {
            float tt  = tr[s];
            int   pos = (int)((pt - tt) * 0.25f);   // == /4.0f exactly; trunc
            if (pos >= 0 && pos < BINS) atomicAdd(&hist[r][BINS - 1 - pos], 1.0f);
        }
    }

    // ---- recurrent weights into registers (packed gate pairs) ----
    u64 wIF[16], wGO[16];
    const int kb = kq * 16;
#pragma unroll
    for (int kk = 0; kk < 16; kk++) {
        int k = kb + kk;
        wIF[kk] = pack2(W_hh[u * H + k],         W_hh[(64  + u) * H + k]);
        wGO[kk] = pack2(W_hh[(128 + u) * H + k], W_hh[(192 + u) * H + k]);
    }
    // every thread is a reducer for row kq -> everyone needs W_ih / bias of its u
    const u64 wihIF = pack2(W_ih[u],        W_ih[64 + u]);
    const u64 wihGO = pack2(W_ih[128 + u],  W_ih[192 + u]);
    const u64 bIF   = pack2(b_ih[u]       + b_hh[u],       b_ih[64 + u]  + b_hh[64 + u]);
    const u64 bGO   = pack2(b_ih[128 + u] + b_hh[128 + u], b_ih[192 + u] + b_hh[192 + u]);

    float c = 0.0f, hout = 0.0f;
    __syncthreads();   // hist + h2s ready

    const int hv_base = kq * 8;    // ulonglong2 index of this thread's k-slice

    for (int t = 0; t < BINS; t++) {
        u64 aIF[ROWS], aGO[ROWS];
#pragma unroll
        for (int r = 0; r < ROWS; r++) { aIF[r] = 0ull; aGO[r] = 0ull; }

#pragma unroll
        for (int i = 0; i < 8; i++) {
#pragma unroll
            for (int r = 0; r < ROWS; r++) {
                ulonglong2 hh = ((const ulonglong2*)h2s[r])[hv_base + i];  // bcast LDS.128
                aIF[r] = ffma2(hh.x, wIF[2 * i],     aIF[r]);
                aGO[r] = ffma2(hh.x, wGO[2 * i],     aGO[r]);
                aIF[r] = ffma2(hh.y, wIF[2 * i + 1], aIF[r]);
                aGO[r] = ffma2(hh.y, wGO[2 * i + 1], aGO[r]);
            }
        }

        // publish partials for rows this thread does NOT own
#pragma unroll
        for (int r = 0; r < ROWS; r++) {
            if (r != kq) {
                int slot = (kq < r) ? kq : kq - 1;
                partial[r][slot][u] = make_ulonglong2(aIF[r], aGO[r]);
            }
        }
        __syncthreads();

        // reduce + activate row r = kq (all 8 warps active)
        {
            const int r = kq;
            u64 accIF = aIF[r], accGO = aGO[r];
#pragma unroll
            for (int m = 0; m < 3; m++) {
                ulonglong2 p = partial[r][m][u];
                accIF = fadd2(accIF, p.x);
                accGO = fadd2(accGO, p.y);
            }
            float x  = hist[r][t];                  // warp-uniform broadcast
            u64   x2 = pack2(x, x);
            accIF = ffma2(x2, wihIF, accIF);
            accGO = ffma2(x2, wihGO, accGO);
            accIF = fadd2(accIF, bIF);
            accGO = fadd2(accGO, bGO);

            float gi, gf, gg, go;
            unpack2(accIF, gi, gf);
            unpack2(accGO, gg, go);
            float si = hsig(gi);
            float sf = hsig(gf);
            float tg = htanh(gg);
            float so = hsig(go);
            c    = sf * c + si * tg;
            hout = so * htanh(c);
            h2s[r][u] = pack2(hout, hout);
        }
        __syncthreads();
    }

    // thread (u, kq) owns (row kq, unit u)
    out[(size_t)(row0 + kq) * H + u] = hout;
}

extern "C" void kernel_launch(void* const* d_in, const int* in_sizes, int n_in,
                              void* d_out, int out_size)
{
    const float* time_  = (const float*)d_in[0];   // [4096, 200]
    const int*   length = (const int*)  d_in[1];   // [4096]
    const float* ptime  = (const float*)d_in[2];   // [4096]
    const float* W_ih   = (const float*)d_in[3];   // [256, 1]
    const float* W_hh   = (const float*)d_in[4];   // [256, 64]
    const float* b_ih   = (const float*)d_in[5];   // [256]
    const float* b_hh   = (const float*)d_in[6];   // [256]
    float* out = (float*)d_out;                    // [4096, 64]

    const int B = in_sizes[1];                     // 4096 rows
    trend_lstm_kernel<<<B / ROWS, 256>>>(time_, length, ptime,
                                         W_ih, W_hh, b_ih, b_hh, out);
}

// round 5
// speedup vs baseline: 1.8281x; 1.4177x over previous
#include <cuda_runtime.h>

typedef unsigned long long u64;

// ---- packed fp32x2 helpers (sm_103a FFMA2 path) ----
__device__ __forceinline__ u64 pack2(float x, float y) {
    u64 r; asm("mov.b64 %0, {%1, %2};" : "=l"(r) : "f"(x), "f"(y)); return r;
}
__device__ __forceinline__ void unpack2(u64 v, float& x, float& y) {
    asm("mov.b64 {%0, %1}, %2;" : "=f"(x), "=f"(y) : "l"(v));
}
__device__ __forceinline__ u64 ffma2(u64 a, u64 b, u64 c) {
    u64 d; asm("fma.rn.f32x2 %0, %1, %2, %3;" : "=l"(d) : "l"(a), "l"(b), "l"(c)); return d;
}
// horizontal add of a packed pair -> scalar
__device__ __forceinline__ float hadd2(u64 v) {
    float lo, hi; unpack2(v, lo, hi); return lo + hi;
}

// HW tanh (single MUFU op)
__device__ __forceinline__ float htanh(float x) {
    float y; asm("tanh.approx.f32 %0, %1;" : "=f"(y) : "f"(x)); return y;
}
__device__ __forceinline__ float hsig(float x) {
    return fmaf(0.5f, htanh(0.5f * x), 0.5f);   // 1 MUFU + 1 FMA
}

constexpr int S_LEN = 200;
constexpr int BINS  = 256;   // T steps
constexpr int H     = 64;
constexpr int ROWS  = 4;     // batch rows per CTA

// 256 threads: thread = (u, kq); u = tid & 63 (hidden unit), kq = tid >> 6
// (k-quarter AND owned row for the reduce/activation phase).
// Packed-k scheme: each gate of unit u accumulates as an fp32x2 pair whose
// lanes hold even-k / odd-k partial sums over k in [kq*16, kq*16+16).
// h is stored UN-duplicated in SMEM -> only 4 broadcast LDS.128 per row.
// Gates are horizontally reduced to scalars BEFORE the SMEM partial exchange,
// keeping partials at one float4 per (row, slice, unit).
__global__ __launch_bounds__(256, 2)
void trend_lstm_kernel(const float* __restrict__ time_,
                       const int*   __restrict__ length_,
                       const float* __restrict__ predict_time_,
                       const float* __restrict__ W_ih,
                       const float* __restrict__ W_hh,
                       const float* __restrict__ b_ih,
                       const float* __restrict__ b_hh,
                       float* __restrict__ out)
{
    __shared__ float  hist[ROWS][BINS];
    __shared__ float  hbuf[ROWS][H];          // plain h (no duplication)
    __shared__ float4 part[ROWS][3][H];       // scalarized gate partials (i,f,g,o)

    const int tid  = threadIdx.x;
    const int u    = tid & 63;
    const int kq   = tid >> 6;
    const int row0 = blockIdx.x * ROWS;

    // ---- init SMEM ----
    {
        float* hf = &hist[0][0];
#pragma unroll
        for (int i = 0; i < ROWS; i++) hf[i * 256 + tid] = 0.0f;
        (&hbuf[0][0])[tid] = 0.0f;            // ROWS*H == 256 entries; h0 = 0
    }
    __syncthreads();

    // ---- fused histogram: 64 threads (lane u) per row kq ----
    {
        const int   r   = kq;
        const float pt  = predict_time_[row0 + r];
        const int   len = length_[row0 + r];
        const float* tr = time_ + (size_t)(row0 + r) * S_LEN;
        for (int s = u; s < len; s += 64) {
            float tt  = tr[s];
            int   pos = (int)((pt - tt) * 0.25f);   // == /4.0f exactly; trunc
            if (pos >= 0 && pos < BINS) atomicAdd(&hist[r][BINS - 1 - pos], 1.0f);
        }
    }

    // ---- recurrent weights, packed over adjacent k (direct 8B gmem loads) ----
    // w[g][p] = ( W_hh[g*64+u][kb+2p], W_hh[g*64+u][kb+2p+1] )
    u64 w[4][8];
    const int kb = kq * 16;
#pragma unroll
    for (int g = 0; g < 4; g++) {
        const float* wr = W_hh + (size_t)(g * H + u) * H + kb;
#pragma unroll
        for (int p = 0; p < 8; p++)
            w[g][p] = *reinterpret_cast<const u64*>(wr + 2 * p);
    }
    // every thread reduces row kq -> needs W_ih / bias of its unit u
    float wih[4], bias[4];
#pragma unroll
    for (int g = 0; g < 4; g++) {
        wih[g]  = W_ih[g * H + u];
        bias[g] = b_ih[g * H + u] + b_hh[g * H + u];
    }

    float c = 0.0f, hout = 0.0f;
    __syncthreads();   // hist + hbuf ready

    for (int t = 0; t < BINS; t++) {
        float own[4];

        // accumulate all 4 rows; publish foreign rows immediately (small live set)
#pragma unroll
        for (int r = 0; r < ROWS; r++) {
            const ulonglong2* hp =
                reinterpret_cast<const ulonglong2*>(&hbuf[r][kb]);   // bcast LDS.128
            u64 a0 = 0ull, a1 = 0ull, a2 = 0ull, a3 = 0ull;
#pragma unroll
            for (int q = 0; q < 4; q++) {
                ulonglong2 hh = hp[q];   // h[kb+4q .. kb+4q+4) as two (even,odd) pairs
                a0 = ffma2(hh.x, w[0][2 * q], a0);
                a1 = ffma2(hh.x, w[1][2 * q], a1);
                a2 = ffma2(hh.x, w[2][2 * q], a2);
                a3 = ffma2(hh.x, w[3][2 * q], a3);
                a0 = ffma2(hh.y, w[0][2 * q + 1], a0);
                a1 = ffma2(hh.y, w[1][2 * q + 1], a1);
                a2 = ffma2(hh.y, w[2][2 * q + 1], a2);
                a3 = ffma2(hh.y, w[3][2 * q + 1], a3);
            }
            float gi = hadd2(a0), gf = hadd2(a1), gg = hadd2(a2), go = hadd2(a3);
            if (r != kq) {
                int slot = (kq < r) ? kq : kq - 1;
                part[r][slot][u] = make_float4(gi, gf, gg, go);   // dense STS.128
            } else {
                own[0] = gi; own[1] = gf; own[2] = gg; own[3] = go;
            }
        }
        __syncthreads();

        // reduce + activate row r = kq (all 8 warps active)
        {
#pragma unroll
            for (int m = 0; m < 3; m++) {
                float4 p = part[kq][m][u];     // dense LDS.128
                own[0] += p.x; own[1] += p.y; own[2] += p.z; own[3] += p.w;
            }
            float x = hist[kq][t];             // warp-uniform broadcast
            float gi = fmaf(x, wih[0], own[0] + bias[0]);
            float gf = fmaf(x, wih[1], own[1] + bias[1]);
            float gg = fmaf(x, wih[2], own[2] + bias[2]);
            float go = fmaf(x, wih[3], own[3] + bias[3]);

            float si = hsig(gi);
            float sf = hsig(gf);
            float tg = htanh(gg);
            float so = hsig(go);
            c    = sf * c + si * tg;
            hout = so * htanh(c);
            hbuf[kq][u] = hout;                // dense STS.32
        }
        __syncthreads();
    }

    // thread (u, kq) owns (row kq, unit u); warp-coalesced store
    out[(size_t)(row0 + kq) * H + u] = hout;
}

extern "C" void kernel_launch(void* const* d_in, const int* in_sizes, int n_in,
                              void* d_out, int out_size)
{
    const float* time_  = (const float*)d_in[0];   // [4096, 200]
    const int*   length = (const int*)  d_in[1];   // [4096]
    const float* ptime  = (const float*)d_in[2];   // [4096]
    const float* W_ih   = (const float*)d_in[3];   // [256, 1]
    const float* W_hh   = (const float*)d_in[4];   // [256, 64]
    const float* b_ih   = (const float*)d_in[5];   // [256]
    const float* b_hh   = (const float*)d_in[6];   // [256]
    float* out = (float*)d_out;                    // [4096, 64]

    const int B = in_sizes[1];                     // 4096 rows
    trend_lstm_kernel<<<B / ROWS, 256>>>(time_, length, ptime,
                                         W_ih, W_hh, b_ih, b_hh, out);
}

// round 8
// speedup vs baseline: 1.8550x; 1.0147x over previous
#include <cuda_runtime.h>

typedef unsigned long long u64;

// ---- packed fp32x2 helpers (sm_103a FFMA2 path) ----
__device__ __forceinline__ void unpack2(u64 v, float& x, float& y) {
    asm("mov.b64 {%0, %1}, %2;" : "=f"(x), "=f"(y) : "l"(v));
}
__device__ __forceinline__ u64 ffma2(u64 a, u64 b, u64 c) {
    u64 d; asm("fma.rn.f32x2 %0, %1, %2, %3;" : "=l"(d) : "l"(a), "l"(b), "l"(c)); return d;
}
__device__ __forceinline__ float hadd2(u64 v) {
    float lo, hi; unpack2(v, lo, hi); return lo + hi;
}

// HW tanh (single MUFU op)
__device__ __forceinline__ float htanh(float x) {
    float y; asm("tanh.approx.f32 %0, %1;" : "=f"(y) : "f"(x)); return y;
}
__device__ __forceinline__ float hsig(float x) {
    return fmaf(0.5f, htanh(0.5f * x), 0.5f);   // 1 MUFU + 1 FMA
}

constexpr int S_LEN = 200;
constexpr int BINS  = 256;   // T steps
constexpr int H     = 64;
constexpr int ROWS  = 4;     // batch rows per CTA
constexpr int HSTR  = 72;    // hbuf row stride (floats): 288B == 32 mod 128 -> conflict-free
constexpr int HISTR = 260;   // hist row stride (floats): 1040B == 16 mod 128 -> conflict-free

// 256 threads, tid = u*4 + kq: u = tid>>2 (hidden unit), kq = tid&3 (k-quarter
// AND owned row). The 4 k-slices of unit u occupy 4 adjacent lanes, so the
// cross-slice gate reduction is a 2-stage warp butterfly (12 SHFL) instead of
// an SMEM exchange + extra barrier.
// XOR trick: accumulator slot a holds row r = a ^ kq, making butterfly
// register indices compile-time and leaving slot 0 = own row kq fully reduced.
// h is double-buffered -> ONE __syncthreads per step.
__global__ __launch_bounds__(256, 2)
void trend_lstm_kernel(const float* __restrict__ time_,
                       const int*   __restrict__ length_,
                       const float* __restrict__ predict_time_,
                       const float* __restrict__ W_ih,
                       const float* __restrict__ W_hh,
                       const float* __restrict__ b_ih,
                       const float* __restrict__ b_hh,
                       float* __restrict__ out)
{
    __shared__ alignas(16) float hist[ROWS * HISTR];
    __shared__ alignas(16) float hbuf[2][ROWS * HSTR];   // double-buffered h

    const int tid  = threadIdx.x;
    const int u    = tid >> 2;
    const int kq   = tid & 3;
    const int row0 = blockIdx.x * ROWS;

    // ---- init SMEM ----
    for (int i = tid; i < ROWS * HISTR; i += 256) hist[i] = 0.0f;
    for (int i = tid; i < 2 * ROWS * HSTR; i += 256) (&hbuf[0][0])[i] = 0.0f;
    __syncthreads();

    // ---- fused histogram: 64 threads (u) per row kq ----
    {
        const float pt  = predict_time_[row0 + kq];
        const int   len = length_[row0 + kq];
        const float* tr = time_ + (size_t)(row0 + kq) * S_LEN;
        for (int s = u; s < len; s += 64) {
            float tt  = tr[s];
            int   pos = (int)((pt - tt) * 0.25f);   // == /4.0f exactly; trunc
            if (pos >= 0 && pos < BINS)
                atomicAdd(&hist[kq * HISTR + (BINS - 1 - pos)], 1.0f);
        }
    }

    // ---- recurrent weights, packed over adjacent k (8B gmem loads) ----
    u64 w[4][8];
    const int kb = kq * 16;
#pragma unroll
    for (int g = 0; g < 4; g++) {
        const float* wr = W_hh + (size_t)(g * H + u) * H + kb;
#pragma unroll
        for (int p = 0; p < 8; p++)
            w[g][p] = *reinterpret_cast<const u64*>(wr + 2 * p);
    }
    float wih[4], bias[4];
#pragma unroll
    for (int g = 0; g < 4; g++) {
        wih[g]  = W_ih[g * H + u];
        bias[g] = b_ih[g * H + u] + b_hh[g * H + u];
    }

    float c = 0.0f, hout = 0.0f;
    __syncthreads();   // hist + hbuf[0] ready

    for (int t = 0; t < BINS; t++) {
        const float* hb  = hbuf[t & 1];
        float*       hbn = hbuf[(t & 1) ^ 1];

        float s[4][4];   // s[a][gate]: partial of row (a ^ kq), slice kq
#pragma unroll
        for (int a = 0; a < ROWS; a++) {
            const int r = a ^ kq;
            const ulonglong2* hp =
                reinterpret_cast<const ulonglong2*>(hb + r * HSTR + kb);
            u64 a0 = 0ull, a1 = 0ull, a2 = 0ull, a3 = 0ull;
#pragma unroll
            for (int q = 0; q < 4; q++) {
                ulonglong2 hh = hp[q];   // 16B, 4 distinct banks across kq groups
                a0 = ffma2(hh.x, w[0][2 * q], a0);
                a1 = ffma2(hh.x, w[1][2 * q], a1);
                a2 = ffma2(hh.x, w[2][2 * q], a2);
                a3 = ffma2(hh.x, w[3][2 * q], a3);
                a0 = ffma2(hh.y, w[0][2 * q + 1], a0);
                a1 = ffma2(hh.y, w[1][2 * q + 1], a1);
                a2 = ffma2(hh.y, w[2][2 * q + 1], a2);
                a3 = ffma2(hh.y, w[3][2 * q + 1], a3);
            }
            s[a][0] = hadd2(a0);
            s[a][1] = hadd2(a1);
            s[a][2] = hadd2(a2);
            s[a][3] = hadd2(a3);
        }

        // 2-stage butterfly over the 4 kq lanes of unit u (rows XOR-aligned)
#pragma unroll
        for (int g = 0; g < 4; g++) {
            s[0][g] += __shfl_xor_sync(0xFFFFFFFFu, s[1][g], 1);
            s[2][g] += __shfl_xor_sync(0xFFFFFFFFu, s[3][g], 1);
        }
#pragma unroll
        for (int g = 0; g < 4; g++)
            s[0][g] += __shfl_xor_sync(0xFFFFFFFFu, s[2][g], 2);

        // activation: thread owns (row kq, unit u)
        {
            float x  = hist[kq * HISTR + t];
            float gi = fmaf(x, wih[0], s[0][0] + bias[0]);
            float gf = fmaf(x, wih[1], s[0][1] + bias[1]);
            float gg = fmaf(x, wih[2], s[0][2] + bias[2]);
            float go = fmaf(x, wih[3], s[0][3] + bias[3]);

            float si = hsig(gi);
            float sf = hsig(gf);
            float tg = htanh(gg);
            float so = hsig(go);
            c    = sf * c + si * tg;
            hout = so * htanh(c);
            hbn[kq * HSTR + u] = hout;   // conflict-free (stride 288B)
        }
        __syncthreads();   // single barrier per step
    }

    out[(size_t)(row0 + kq) * H + u] = hout;
}

extern "C" void kernel_launch(void* const* d_in, const int* in_sizes, int n_in,
                              void* d_out, int out_size)
{
    const float* time_  = (const float*)d_in[0];   // [4096, 200]
    const int*   length = (const int*)  d_in[1];   // [4096]
    const float* ptime  = (const float*)d_in[2];   // [4096]
    const float* W_ih   = (const float*)d_in[3];   // [256, 1]
    const float* W_hh   = (const float*)d_in[4];   // [256, 64]
    const float* b_ih   = (const float*)d_in[5];   // [256]
    const float* b_hh   = (const float*)d_in[6];   // [256]
    float* out = (float*)d_out;                    // [4096, 64]

    const int B = in_sizes[1];                     // 4096 rows
    trend_lstm_kernel<<<B / ROWS, 256>>>(time_, length, ptime,
                                         W_ih, W_hh, b_ih, b_hh, out);
}